// round 3
// baseline (speedup 1.0000x reference)
#include <cuda_runtime.h>
#include <cuda_bf16.h>

// PhysicsRouter fused, split-C version.
// logits = X @ W^T + mass*bias; softmax; top-2; aux loss.
// X [16384, 4096] f32, mass [16384], W [4, 4096], bias [4].
// Output (f32): [0,65536) logits | [65536,98304) top_k_idx | [98304] aux | [98305,131073) top_k_w
//
// Each block = 16 tokens, 4 warps; warp s owns columns [s*1024, (s+1)*1024).
// Gate reuse x16 per load (gate L2 traffic = 64 MB total) AND 4096 warps of
// memory-level parallelism (vs 1024 in the non-split GROUP=16 version).

#define C_DIM 4096
#define E_DIM 4
#define N_TOK 16384
#define GROUP 16                  // tokens per block
#define SPLIT 4                   // warps per token group (column split)
#define BLOCK_THREADS (SPLIT * 32)
#define GRID_BLOCKS (N_TOK / GROUP)          // 1024
#define COLS_PER_WARP (C_DIM / SPLIT)        // 1024
#define ITERS (COLS_PER_WARP / 128)          // 8

__device__ float g_partial[GRID_BLOCKS][E_DIM];
__device__ unsigned int g_count = 0;  // wraps to 0 each full grid -> graph-replay safe

__global__ __launch_bounds__(BLOCK_THREADS, 5)
void router_fused(const float* __restrict__ X,
                  const float* __restrict__ mass,
                  const float* __restrict__ W,
                  const float* __restrict__ bias,
                  float* __restrict__ out)
{
    const int tid  = threadIdx.x;
    const int warp = tid >> 5;           // split id: 0..3
    const int lane = tid & 31;
    const long token0 = (long)blockIdx.x * GROUP;
    const int cbase = warp * COLS_PER_WARP;

    float acc[GROUP][E_DIM];
#pragma unroll
    for (int t = 0; t < GROUP; t++)
#pragma unroll
        for (int e = 0; e < E_DIM; e++) acc[t][e] = 0.0f;

    // 8 iterations x 128 columns per warp. Gate float4s reused across 16 tokens.
#pragma unroll 1
    for (int it = 0; it < ITERS; ++it) {
        const int col = cbase + it * 128 + lane * 4;
        float4 g[E_DIM];
#pragma unroll
        for (int e = 0; e < E_DIM; e++)
            g[e] = __ldg((const float4*)(W + e * C_DIM + col));
#pragma unroll
        for (int t = 0; t < GROUP; t++) {
            const float4 x = __ldg((const float4*)(X + (token0 + t) * C_DIM + col));
#pragma unroll
            for (int e = 0; e < E_DIM; e++) {
                float a = acc[t][e];
                a = fmaf(x.x, g[e].x, a);
                a = fmaf(x.y, g[e].y, a);
                a = fmaf(x.z, g[e].z, a);
                a = fmaf(x.w, g[e].w, a);
                acc[t][e] = a;
            }
        }
    }

    // Butterfly-reduce all 64 accumulators across the warp.
#pragma unroll
    for (int t = 0; t < GROUP; t++)
#pragma unroll
        for (int e = 0; e < E_DIM; e++)
#pragma unroll
            for (int s = 16; s > 0; s >>= 1)
                acc[t][e] += __shfl_xor_sync(0xFFFFFFFFu, acc[t][e], s);

    // Lane t (t < GROUP) holds token t's partial for this column slice.
    float l[E_DIM] = {0.f, 0.f, 0.f, 0.f};
#pragma unroll
    for (int t = 0; t < GROUP; t++) {
        if (lane == t) {
#pragma unroll
            for (int e = 0; e < E_DIM; e++) l[e] = acc[t][e];
        }
    }

    // Combine the 4 column-slice partials through shared memory.
    __shared__ float4 s_part[SPLIT][GROUP];
    if (lane < GROUP) {
        float4 v; v.x = l[0]; v.y = l[1]; v.z = l[2]; v.w = l[3];
        s_part[warp][lane] = v;
    }
    __syncthreads();

    __shared__ bool s_is_last;

    if (warp == 0) {
        float p[E_DIM] = {0.f, 0.f, 0.f, 0.f};

        if (lane < GROUP) {
            const float4 a0 = s_part[0][lane];
            const float4 a1 = s_part[1][lane];
            const float4 a2 = s_part[2][lane];
            const float4 a3 = s_part[3][lane];
            float q0 = (a0.x + a1.x) + (a2.x + a3.x);
            float q1 = (a0.y + a1.y) + (a2.y + a3.y);
            float q2 = (a0.z + a1.z) + (a2.z + a3.z);
            float q3 = (a0.w + a1.w) + (a2.w + a3.w);

            const long token = token0 + lane;
            const float m = __ldg(mass + token);
            const float4 b = __ldg((const float4*)bias);
            q0 = fmaf(m, b.x, q0);
            q1 = fmaf(m, b.y, q1);
            q2 = fmaf(m, b.z, q2);
            q3 = fmaf(m, b.w, q3);

            float4 lo; lo.x = q0; lo.y = q1; lo.z = q2; lo.w = q3;
            *(float4*)(out + token * E_DIM) = lo;

            const float mx = fmaxf(fmaxf(q0, q1), fmaxf(q2, q3));
            p[0] = expf(q0 - mx);
            p[1] = expf(q1 - mx);
            p[2] = expf(q2 - mx);
            p[3] = expf(q3 - mx);
            const float inv = 1.0f / (p[0] + p[1] + p[2] + p[3]);
            p[0] *= inv; p[1] *= inv; p[2] *= inv; p[3] *= inv;

            // top-2, lowest-index tie break (strict > keeps earlier index)
            int i1 = 0; float v1 = p[0];
#pragma unroll
            for (int e = 1; e < E_DIM; e++)
                if (p[e] > v1) { v1 = p[e]; i1 = e; }
            int i2 = -1; float v2 = -1.0f;
#pragma unroll
            for (int e = 0; e < E_DIM; e++)
                if (e != i1 && p[e] > v2) { v2 = p[e]; i2 = e; }

            float* out_idx = out + (long)N_TOK * E_DIM;
            float* out_w   = out + (long)N_TOK * E_DIM + (long)N_TOK * 2 + 1;
            out_idx[token * 2 + 0] = (float)i1;
            out_idx[token * 2 + 1] = (float)i2;
            out_w[token * 2 + 0]   = v1;
            out_w[token * 2 + 1]   = v2;
        }

        // Expert importance: butterfly over warp 0 (lanes >= GROUP contribute 0).
#pragma unroll
        for (int e = 0; e < E_DIM; e++)
#pragma unroll
            for (int s = 16; s > 0; s >>= 1)
                p[e] += __shfl_xor_sync(0xFFFFFFFFu, p[e], s);

        if (lane == 0) {
#pragma unroll
            for (int e = 0; e < E_DIM; e++)
                g_partial[blockIdx.x][e] = p[e];
            __threadfence();
            const unsigned int v = atomicInc(&g_count, GRID_BLOCKS - 1);
            s_is_last = (v == GRID_BLOCKS - 1);
        }
    }
    __syncthreads();

    // ---- last block finalizes aux loss ----
    if (s_is_last) {
        __shared__ double s_sum[BLOCK_THREADS];
        const int e = tid & 3;
        const int chunk = tid >> 2;                   // 0..31
        const int per = GRID_BLOCKS / 32;             // 32
        double s = 0.0;
        for (int j = chunk * per; j < (chunk + 1) * per; j++)
            s += (double)g_partial[j][e];
        s_sum[tid] = s;
        __syncthreads();
        if (tid < E_DIM) {
            double imp = 0.0;
#pragma unroll
            for (int k = 0; k < 32; k++)
                imp += s_sum[e + 4 * k];              // e == tid here
            s_sum[tid] = imp;
        }
        __syncthreads();
        if (tid == 0) {
            const double target = (double)N_TOK / (double)E_DIM;
            double loss = 0.0;
#pragma unroll
            for (int k = 0; k < E_DIM; k++) {
                const double d = s_sum[k] - target;
                loss += d * d;
            }
            out[(long)N_TOK * E_DIM + (long)N_TOK * 2] = (float)(loss / E_DIM);
        }
    }
}

extern "C" void kernel_launch(void* const* d_in, const int* in_sizes, int n_in,
                              void* d_out, int out_size)
{
    const float* X    = (const float*)d_in[0];
    const float* mass = (const float*)d_in[1];
    const float* W    = (const float*)d_in[2];
    const float* bias = (const float*)d_in[3];
    float* out = (float*)d_out;

    router_fused<<<GRID_BLOCKS, BLOCK_THREADS>>>(X, mass, W, bias, out);
}

// round 4
// speedup vs baseline: 1.7310x; 1.7310x over previous
#include <cuda_runtime.h>
#include <cuda_bf16.h>

// PhysicsRouter, cp.async pipelined version.
// logits = X @ W^T + mass*bias; softmax; top-2; aux loss.
// X [16384, 4096] f32, mass [16384], W [4, 4096], bias [4].
// Output (f32): [0,65536) logits | [65536,98304) top_k_idx | [98304] aux | [98305,131073) top_k_w
//
// Block = 16 tokens, 256 threads. X is streamed through a 5-deep smem pipeline
// via cp.async.cg (no register cost for in-flight loads -> deep MLP), gate W
// stays L1-resident (cp.async.cg bypasses L1 for X). Each warp computes 2 tokens.

#define C_DIM 4096
#define E_DIM 4
#define N_TOK 16384
#define TPB 16                         // tokens per block
#define BLOCK_THREADS 256
#define NWARPS (BLOCK_THREADS / 32)    // 8
#define GRID_BLOCKS (N_TOK / TPB)      // 1024
#define STAGE_COLS 128
#define NSTAGES (C_DIM / STAGE_COLS)   // 32
#define DEPTH 5
#define STAGE_BYTES (TPB * STAGE_COLS * 4)   // 8192

__device__ float g_partial[GRID_BLOCKS][E_DIM];
__device__ unsigned int g_count = 0;   // wraps to 0 each full grid -> graph-replay safe

__device__ __forceinline__ void cp_async16(unsigned int saddr, const float* gptr) {
    asm volatile("cp.async.cg.shared.global [%0], [%1], 16;" :: "r"(saddr), "l"(gptr));
}
__device__ __forceinline__ void cp_commit() {
    asm volatile("cp.async.commit_group;");
}
template <int N>
__device__ __forceinline__ void cp_wait() {
    asm volatile("cp.async.wait_group %0;" :: "n"(N));
}

__global__ __launch_bounds__(BLOCK_THREADS)
void router_pipe(const float* __restrict__ X,
                 const float* __restrict__ mass,
                 const float* __restrict__ W,
                 const float* __restrict__ bias,
                 float* __restrict__ out)
{
    __shared__ float sx[DEPTH][TPB][STAGE_COLS];
    __shared__ float s_imp[NWARPS][E_DIM];
    __shared__ bool  s_is_last;

    const int tid  = threadIdx.x;
    const int warp = tid >> 5;
    const int lane = tid & 31;
    const long token0 = (long)blockIdx.x * TPB;

    // ---- staging assignment: thread copies 32 B of one token row per stage ----
    const int ld_tok = tid >> 4;       // 0..15
    const int ld_seg = tid & 15;       // 0..15 (32 B each -> 512 B per token-stage)
    const float* xsrc0 = X + (token0 + ld_tok) * (long)C_DIM + ld_seg * 8;
    const unsigned int sdst0 = (unsigned int)__cvta_generic_to_shared(
        &sx[0][ld_tok][ld_seg * 8]);

    // ---- prologue: fill DEPTH-1 stages ----
#pragma unroll
    for (int s = 0; s < DEPTH - 1; s++) {
        const float* g = xsrc0 + s * STAGE_COLS;
        const unsigned int d = sdst0 + s * STAGE_BYTES;
        cp_async16(d, g);
        cp_async16(d + 16, g + 4);
        cp_commit();
    }

    // ---- mainloop ----
    const int t0 = warp * 2;
    float acc0[E_DIM] = {0.f, 0.f, 0.f, 0.f};
    float acc1[E_DIM] = {0.f, 0.f, 0.f, 0.f};

#pragma unroll 1
    for (int s = 0; s < NSTAGES; s++) {
        cp_wait<DEPTH - 2>();          // stage s landed
        __syncthreads();

        const int buf = s % DEPTH;
        const int col = s * STAGE_COLS + lane * 4;
        float4 g[E_DIM];
#pragma unroll
        for (int e = 0; e < E_DIM; e++)
            g[e] = __ldg((const float4*)(W + e * C_DIM + col));   // L1-resident

        const float4 x0 = *(const float4*)&sx[buf][t0][lane * 4];
        const float4 x1 = *(const float4*)&sx[buf][t0 + 1][lane * 4];
#pragma unroll
        for (int e = 0; e < E_DIM; e++) {
            float a = acc0[e];
            a = fmaf(x0.x, g[e].x, a);
            a = fmaf(x0.y, g[e].y, a);
            a = fmaf(x0.z, g[e].z, a);
            a = fmaf(x0.w, g[e].w, a);
            acc0[e] = a;
            float b = acc1[e];
            b = fmaf(x1.x, g[e].x, b);
            b = fmaf(x1.y, g[e].y, b);
            b = fmaf(x1.z, g[e].z, b);
            b = fmaf(x1.w, g[e].w, b);
            acc1[e] = b;
        }

        __syncthreads();               // everyone done reading buf (s) before refill

        const int ns = s + DEPTH - 1;
        if (ns < NSTAGES) {
            const float* gsrc = xsrc0 + ns * STAGE_COLS;
            const unsigned int d = sdst0 + (ns % DEPTH) * STAGE_BYTES;
            cp_async16(d, gsrc);
            cp_async16(d + 16, gsrc + 4);
        }
        cp_commit();                   // keep group count consistent past the end
    }

    // ---- butterfly reduce both tokens' accumulators across the warp ----
#pragma unroll
    for (int e = 0; e < E_DIM; e++) {
#pragma unroll
        for (int s = 16; s > 0; s >>= 1) {
            acc0[e] += __shfl_xor_sync(0xFFFFFFFFu, acc0[e], s);
            acc1[e] += __shfl_xor_sync(0xFFFFFFFFu, acc1[e], s);
        }
    }

    // ---- epilogue: lane 0 of each warp handles its 2 tokens ----
    if (lane == 0) {
        const float4 b = __ldg((const float4*)bias);
        float psum[E_DIM];
#pragma unroll
        for (int e = 0; e < E_DIM; e++) psum[e] = 0.0f;

#pragma unroll
        for (int k = 0; k < 2; k++) {
            const long token = token0 + t0 + k;
            float q0 = k ? acc1[0] : acc0[0];
            float q1 = k ? acc1[1] : acc0[1];
            float q2 = k ? acc1[2] : acc0[2];
            float q3 = k ? acc1[3] : acc0[3];

            const float m = __ldg(mass + token);
            q0 = fmaf(m, b.x, q0);
            q1 = fmaf(m, b.y, q1);
            q2 = fmaf(m, b.z, q2);
            q3 = fmaf(m, b.w, q3);

            float4 lo; lo.x = q0; lo.y = q1; lo.z = q2; lo.w = q3;
            *(float4*)(out + token * E_DIM) = lo;

            const float mx = fmaxf(fmaxf(q0, q1), fmaxf(q2, q3));
            float p[E_DIM];
            p[0] = expf(q0 - mx);
            p[1] = expf(q1 - mx);
            p[2] = expf(q2 - mx);
            p[3] = expf(q3 - mx);
            const float inv = 1.0f / (p[0] + p[1] + p[2] + p[3]);
#pragma unroll
            for (int e = 0; e < E_DIM; e++) { p[e] *= inv; psum[e] += p[e]; }

            // top-2, lowest-index tie break (strict > keeps earlier index)
            int i1 = 0; float v1 = p[0];
#pragma unroll
            for (int e = 1; e < E_DIM; e++)
                if (p[e] > v1) { v1 = p[e]; i1 = e; }
            int i2 = -1; float v2 = -1.0f;
#pragma unroll
            for (int e = 0; e < E_DIM; e++)
                if (e != i1 && p[e] > v2) { v2 = p[e]; i2 = e; }

            float* out_idx = out + (long)N_TOK * E_DIM;
            float* out_w   = out + (long)N_TOK * E_DIM + (long)N_TOK * 2 + 1;
            out_idx[token * 2 + 0] = (float)i1;
            out_idx[token * 2 + 1] = (float)i2;
            out_w[token * 2 + 0]   = v1;
            out_w[token * 2 + 1]   = v2;
        }

#pragma unroll
        for (int e = 0; e < E_DIM; e++) s_imp[warp][e] = psum[e];
    }
    __syncthreads();

    if (tid == 0) {
        float pb[E_DIM] = {0.f, 0.f, 0.f, 0.f};
#pragma unroll
        for (int w = 0; w < NWARPS; w++)
#pragma unroll
            for (int e = 0; e < E_DIM; e++) pb[e] += s_imp[w][e];
#pragma unroll
        for (int e = 0; e < E_DIM; e++) g_partial[blockIdx.x][e] = pb[e];
        __threadfence();
        const unsigned int v = atomicInc(&g_count, GRID_BLOCKS - 1);
        s_is_last = (v == GRID_BLOCKS - 1);
    }
    __syncthreads();

    // ---- last block finalizes aux loss ----
    if (s_is_last) {
        __shared__ double s_sum[BLOCK_THREADS];
        const int e = tid & 3;
        const int chunk = tid >> 2;                 // 0..63
        const int per = GRID_BLOCKS / (BLOCK_THREADS / 4);   // 16
        double s = 0.0;
        for (int j = chunk * per; j < (chunk + 1) * per; j++)
            s += (double)g_partial[j][e];
        s_sum[tid] = s;
        __syncthreads();
        if (tid < E_DIM) {
            double imp = 0.0;
#pragma unroll
            for (int k = 0; k < BLOCK_THREADS / 4; k++)
                imp += s_sum[e + 4 * k];            // e == tid here
            s_sum[tid] = imp;
        }
        __syncthreads();
        if (tid == 0) {
            const double target = (double)N_TOK / (double)E_DIM;
            double loss = 0.0;
#pragma unroll
            for (int k = 0; k < E_DIM; k++) {
                const double d = s_sum[k] - target;
                loss += d * d;
            }
            out[(long)N_TOK * E_DIM + (long)N_TOK * 2] = (float)(loss / E_DIM);
        }
    }
}

extern "C" void kernel_launch(void* const* d_in, const int* in_sizes, int n_in,
                              void* d_out, int out_size)
{
    const float* X    = (const float*)d_in[0];
    const float* mass = (const float*)d_in[1];
    const float* W    = (const float*)d_in[2];
    const float* bias = (const float*)d_in[3];
    float* out = (float*)d_out;

    router_pipe<<<GRID_BLOCKS, BLOCK_THREADS>>>(X, mass, W, bias, out);
}